// round 11
// baseline (speedup 1.0000x reference)
#include <cuda_runtime.h>
#include <math.h>

#define B   32
#define NF  128
#define DE  256
#define DH  512
#define G   2
#define SL  8

// ---- device scratch (no allocations allowed) ----
__device__ float g_query[B * DE];
__device__ float g_attin[B * NF * G];
__device__ float g_P[B * NF * NF];       // M @ M (integer counts as float)
__device__ float g_R[B * NF * NF];       // 0.81*M + 0.729*P
__device__ float g_finalT[B * NF * NF];  // final mask, transposed [b][m][n]
__device__ float g_sig[B * NF * NF];     // sigmoid(fe . q), layout [b][m][n]
// intra-launch ordering (reset by k3_final each replay; static-init 0)
__device__ unsigned g_ctr_q[B];          // query chunks done per batch (==8)
__device__ unsigned g_bitP_done[B];      // bitP done flag per batch

__device__ __forceinline__ void cp_async16(void* smem_dst, const void* gmem_src) {
    unsigned sa = (unsigned)__cvta_generic_to_shared(smem_dst);
    asm volatile("cp.async.ca.shared.global [%0], [%1], 16;" :: "r"(sa), "l"(gmem_src));
}

// ============================================================================
// Fused kernel: grid(4640), block(256).  Producers at lowest bids (never spin).
//   bids    0- 255 : query tile (b=bid>>3, dchunk=bid&7)  -> g_ctr_q[b]++
//   bids  256- 287 : bitP (P=M@M popcount, R, att_in)     -> g_bitP_done[b]=1
//   bids  288- 543 : prepB (final = M+0.9P+P@R -> finalT)  spins g_bitP_done[b]
//   bids  544-4639 : sigma stream                          spins g_ctr_q[b]==8
// ============================================================================
__global__ __launch_bounds__(256) void k2_fused(
    const float* __restrict__ relmask, const float* __restrict__ fe,
    const float* __restrict__ c_i, const float* __restrict__ W,
    const float* __restrict__ bias,
    const float* __restrict__ att_stack, const float* __restrict__ stack_ptr)
{
    __shared__ __align__(16) char shraw[49152];
    int bid = blockIdx.x;
    int t = threadIdx.x;

    if (bid < 256) {
        // ---------------- query tile ----------------
        int b  = bid >> 3;
        int d0 = (bid & 7) * 32;
        float* qc = (float*)shraw;
        qc[t]       = c_i[b * DH + t];
        qc[t + 256] = c_i[b * DH + t + 256];
        __syncthreads();

        int w = t >> 5, lane = t & 31;
        const float4* qc4 = (const float4*)qc;

        float4 wv[4][4];
        #pragma unroll
        for (int i = 0; i < 4; i++) {
            int d = d0 + w * 4 + i;
            const float4* Wr = (const float4*)(W + (size_t)d * DH);
            #pragma unroll
            for (int jj = 0; jj < 4; jj++)
                wv[i][jj] = Wr[lane + 32 * jj];
        }
        #pragma unroll
        for (int i = 0; i < 4; i++) {
            int d = d0 + w * 4 + i;
            float s = 0.f;
            #pragma unroll
            for (int jj = 0; jj < 4; jj++) {
                float4 q = qc4[lane + 32 * jj];
                s += wv[i][jj].x * q.x + wv[i][jj].y * q.y
                   + wv[i][jj].z * q.z + wv[i][jj].w * q.w;
            }
            #pragma unroll
            for (int o = 16; o; o >>= 1) s += __shfl_xor_sync(~0u, s, o);
            if (lane == 0) g_query[b * DE + d] = s + bias[d];
        }
        __threadfence();
        __syncthreads();
        if (t == 0) atomicAdd(&g_ctr_q[b], 1u);
        return;
    }

    if (bid < 288) {
        // ---------------- bitP (+ att_in) ----------------
        int b = bid - 256;
        const float* Mb = relmask + (size_t)b * NF * NF;

        unsigned (*rowbits)[4] = (unsigned(*)[4])shraw;            // 2KB
        unsigned (*colbits)[5] = (unsigned(*)[5])(shraw + 2048);   // 2.5KB

        int w = t >> 5, lane = t & 31;

        // pack rows: batch 8 loads before ballots -> MLP 8
        #pragma unroll
        for (int g8 = 0; g8 < 8; g8++) {
            float v[8];
            #pragma unroll
            for (int i = 0; i < 8; i++) {
                int Wd = w + 8 * (8 * g8 + i);
                int r = Wd >> 2, ww = Wd & 3;
                v[i] = Mb[r * NF + ww * 32 + lane];
            }
            #pragma unroll
            for (int i = 0; i < 8; i++) {
                int Wd = w + 8 * (8 * g8 + i);
                int r = Wd >> 2, ww = Wd & 3;
                unsigned bal = __ballot_sync(~0u, v[i] != 0.f);
                if (lane == 0) rowbits[r][ww] = bal;
            }
        }

        // att_in (tiny; consumed only by k3_final)
        {
            int n = t >> 1, g = t & 1;
            const float* as = att_stack + (((size_t)b * NF + n) * G + g) * SL;
            const float* sp = stack_ptr + b * SL;
            float s = 0.f;
            #pragma unroll
            for (int ss = 0; ss < SL; ss++) s += as[ss] * sp[ss];
            g_attin[(b * NF + n) * G + g] = s;
        }
        __syncthreads();

        // bit transpose
        for (int p = t; p < 512; p += 256) {
            int m = p >> 2, ww = p & 3;
            unsigned x = 0;
            #pragma unroll
            for (int j = 0; j < 32; j++)
                x |= (((rowbits[32 * ww + j][m >> 5] >> (m & 31)) & 1u) << j);
            colbits[m][ww] = x;
        }
        __syncthreads();

        float* Pb = g_P + (size_t)b * NF * NF;
        float* Rb = g_R + (size_t)b * NF * NF;
        for (int o = t; o < NF * NF; o += 256) {
            int n = o >> 7, m = o & 127;
            unsigned c = __popc(rowbits[n][0] & colbits[m][0])
                       + __popc(rowbits[n][1] & colbits[m][1])
                       + __popc(rowbits[n][2] & colbits[m][2])
                       + __popc(rowbits[n][3] & colbits[m][3]);
            float p = (float)c;
            float mm = (float)((rowbits[n][m >> 5] >> (m & 31)) & 1u);
            Pb[o] = p;
            Rb[o] = 0.81f * mm + 0.729f * p;
        }
        __threadfence();
        __syncthreads();
        if (t == 0) atomicExch(&g_bitP_done[b], 1u);
        return;
    }

    if (bid < 544) {
        // ---------------- prepB ----------------
        int id = bid - 288;
        int b  = id >> 3;
        int n0 = (id & 7) * 16;
        const float* Pb = g_P + (size_t)b * NF * NF;
        const float* Rb = g_R + (size_t)b * NF * NF;
        const float* Mb = relmask + (size_t)b * NF * NF;

        if (t == 0) {
            while (*(volatile unsigned*)&g_bitP_done[b] == 0u) __nanosleep(32);
            __threadfence();
        }
        __syncthreads();

        float (*csh)[NF] = (float(*)[NF])shraw;                 // 8KB: P rows
        float (*msm)[NF] = (float(*)[NF])(shraw + 8192);        // 8KB: M rows
        float (*msh)[32][NF] = (float(*)[32][NF])(shraw + 16384); // 32KB

        {
            const float4* srcP = (const float4*)(Pb + (size_t)n0 * NF);
            const float4* srcM = (const float4*)(Mb + (size_t)n0 * NF);
            float4* dstP = (float4*)&csh[0][0];
            float4* dstM = (float4*)&msm[0][0];
            cp_async16(dstP + t,       srcP + t);
            cp_async16(dstP + t + 256, srcP + t + 256);
            cp_async16(dstM + t,       srcM + t);
            cp_async16(dstM + t + 256, srcM + t + 256);
        }
        {
            const float4* src = (const float4*)Rb;
            float4* dst = (float4*)&msh[0][0][0];
            #pragma unroll
            for (int i = 0; i < 4; i++)
                cp_async16(dst + t + 256 * i, src + t + 256 * i);
        }
        asm volatile("cp.async.commit_group;");
        asm volatile("cp.async.wait_group 0;");
        __syncthreads();

        int tn = (t >> 5) * 2;
        int tm = (t & 31) * 4;

        float acc0[4] = {}, acc1[4] = {};
        for (int kt = 0; kt < 4; kt++) {
            if (kt < 3) {
                const float4* src = (const float4*)(Rb + (size_t)(kt + 1) * 32 * NF);
                float4* dst = (float4*)&msh[(kt + 1) & 1][0][0];
                #pragma unroll
                for (int i = 0; i < 4; i++)
                    cp_async16(dst + t + 256 * i, src + t + 256 * i);
                asm volatile("cp.async.commit_group;");
                asm volatile("cp.async.wait_group 1;");
            } else {
                asm volatile("cp.async.wait_group 0;");
            }
            __syncthreads();

            const float (*mb)[NF] = msh[kt & 1];
            #pragma unroll
            for (int kk4 = 0; kk4 < 8; kk4++) {
                float cva[4], cvb[4];
                *(float4*)cva = *(const float4*)&csh[tn + 0][kt * 32 + kk4 * 4];
                *(float4*)cvb = *(const float4*)&csh[tn + 1][kt * 32 + kk4 * 4];
                #pragma unroll
                for (int j = 0; j < 4; j++) {
                    float4 mv = *(const float4*)&mb[kk4 * 4 + j][tm];
                    acc0[0] += cva[j] * mv.x; acc0[1] += cva[j] * mv.y;
                    acc0[2] += cva[j] * mv.z; acc0[3] += cva[j] * mv.w;
                    acc1[0] += cvb[j] * mv.x; acc1[1] += cvb[j] * mv.y;
                    acc1[2] += cvb[j] * mv.z; acc1[3] += cvb[j] * mv.w;
                }
            }
            __syncthreads();
        }

        float4 f0, f1;
        {
            float4 mm = *(const float4*)&msm[tn + 0][tm];
            float4 pp = *(const float4*)&csh[tn + 0][tm];
            f0.x = mm.x + 0.9f * pp.x + acc0[0];
            f0.y = mm.y + 0.9f * pp.y + acc0[1];
            f0.z = mm.z + 0.9f * pp.z + acc0[2];
            f0.w = mm.w + 0.9f * pp.w + acc0[3];
            mm = *(const float4*)&msm[tn + 1][tm];
            pp = *(const float4*)&csh[tn + 1][tm];
            f1.x = mm.x + 0.9f * pp.x + acc1[0];
            f1.y = mm.y + 0.9f * pp.y + acc1[1];
            f1.z = mm.z + 0.9f * pp.z + acc1[2];
            f1.w = mm.w + 0.9f * pp.w + acc1[3];
        }
        __syncthreads();
        *(float4*)&csh[tn + 0][tm] = f0;
        *(float4*)&csh[tn + 1][tm] = f1;
        __syncthreads();
        {
            int m = t >> 1, half = (t & 1) * 8;
            float v[8];
            #pragma unroll
            for (int i = 0; i < 8; i++) v[i] = csh[half + i][m];
            float* dstT = g_finalT + ((size_t)b * NF + m) * NF + n0 + half;
            *(float4*)&dstT[0] = make_float4(v[0], v[1], v[2], v[3]);
            *(float4*)&dstT[4] = make_float4(v[4], v[5], v[6], v[7]);
        }
        return;
    }

    // ---------------- sigma stream ----------------
    int id = bid - 544;
    int b = id >> 7;
    int m = id & 127;
    float* qsh = (float*)shraw;          // 1KB
    float* sig = qsh + DE;               // 0.5KB

    if (t == 0) {
        while (*(volatile unsigned*)&g_ctr_q[b] < 8u) __nanosleep(32);
        __threadfence();
    }
    __syncthreads();
    qsh[t] = g_query[b * DE + t];
    __syncthreads();

    int w = t >> 5, lane = t & 31;
    int qq = lane >> 3, sub = lane & 7;
    const float4* qp = (const float4*)qsh;
    const float* febase = fe + (((size_t)b * NF) * NF + m) * DE;

    float4 cur[8];
    {
        const float4* row = (const float4*)(febase + (size_t)(w + 8 * qq) * NF * DE);
        #pragma unroll
        for (int c = 0; c < 8; c++) cur[c] = __ldcs(&row[sub + 8 * c]);
    }

    #pragma unroll
    for (int j = 0; j < 4; j++) {
        float4 nxt[8];
        if (j < 3) {
            int n2 = w + 8 * (4 * (j + 1) + qq);
            const float4* row = (const float4*)(febase + (size_t)n2 * NF * DE);
            #pragma unroll
            for (int c = 0; c < 8; c++) nxt[c] = __ldcs(&row[sub + 8 * c]);
        }

        float sA = 0.f, sB = 0.f;
        #pragma unroll
        for (int c = 0; c < 8; c += 2) {
            float4 q0 = qp[sub + 8 * c];
            float4 q1 = qp[sub + 8 * (c + 1)];
            sA += cur[c].x * q0.x + cur[c].y * q0.y
                + cur[c].z * q0.z + cur[c].w * q0.w;
            sB += cur[c+1].x * q1.x + cur[c+1].y * q1.y
                + cur[c+1].z * q1.z + cur[c+1].w * q1.w;
        }
        float s = sA + sB;
        s += __shfl_xor_sync(~0u, s, 1);
        s += __shfl_xor_sync(~0u, s, 2);
        s += __shfl_xor_sync(~0u, s, 4);
        int n = w + 8 * (4 * j + qq);
        if (sub == 0) sig[n] = 1.f / (1.f + __expf(-s));

        #pragma unroll
        for (int c = 0; c < 8; c++) cur[c] = nxt[c];
    }
    __syncthreads();
    if (t < NF)
        g_sig[((size_t)b * NF + m) * NF + t] = sig[t];
}

// ============================================================================
// Kernel 3: masked contraction + norm + blend + all outputs.
// Also resets the ordering counters for the next graph replay.
// grid(B), block(512).
// ============================================================================
__global__ __launch_bounds__(512) void k3_final(
    const float* __restrict__ att_stack, const float* __restrict__ stack_ptr,
    float* __restrict__ out)
{
    int b = blockIdx.x;
    int t = threadIdx.x;
    __shared__ float ash[NF * G];
    __shared__ float att[NF * G];
    __shared__ float norm[G];
    __shared__ float sps[SL];

    if (t < NF * G) ash[t] = g_attin[b * NF * G + t];
    if (t < SL) sps[t] = stack_ptr[b * SL + t];
    __syncthreads();

    int w = t >> 5, lane = t & 31;
    const float4* ap = (const float4*)ash;
    float4 a01 = ap[2 * lane], a23 = ap[2 * lane + 1];

    #pragma unroll
    for (int r = 0; r < 8; r++) {
        int m = w + 16 * r;
        const float4* fr = (const float4*)(g_finalT + ((size_t)b * NF + m) * NF);
        const float4* sr = (const float4*)(g_sig    + ((size_t)b * NF + m) * NF);
        float4 f = fr[lane];
        float4 s = sr[lane];
        float w0 = f.x * s.x, w1 = f.y * s.y, w2 = f.z * s.z, w3 = f.w * s.w;
        float p0 = w0 * a01.x + w1 * a01.z + w2 * a23.x + w3 * a23.z;
        float p1 = w0 * a01.y + w1 * a01.w + w2 * a23.y + w3 * a23.w;
        #pragma unroll
        for (int o = 16; o; o >>= 1) {
            p0 += __shfl_xor_sync(~0u, p0, o);
            p1 += __shfl_xor_sync(~0u, p1, o);
        }
        if (lane == 0) { att[m * 2] = p0; att[m * 2 + 1] = p1; }
    }
    __syncthreads();

    if (t < 64) {
        int g = t >> 5, ln = t & 31;
        float mx = -1e30f;
        for (int i = ln; i < NF; i += 32) mx = fmaxf(mx, att[i * G + g]);
        #pragma unroll
        for (int o = 16; o; o >>= 1) mx = fmaxf(mx, __shfl_xor_sync(~0u, mx, o));
        if (ln == 0) norm[g] = (mx <= 1.f) ? 1.f : mx;
    }
    __syncthreads();

    const float* asb = att_stack + (size_t)b * NF * G * SL;
    float* ob = out + (size_t)b * NF * G * SL;
    for (int idx = t; idx < NF * G * SL; idx += 512) {
        int s = idx & 7;
        int g = (idx >> 3) & 1;
        int n = idx >> 4;
        float a  = att[n * G + g] / norm[g];
        float sp = sps[s];
        ob[idx] = a * sp + asb[idx] * (1.f - sp);
    }
    if (t < SL) out[(size_t)B * NF * G * SL + b * SL + t] = sps[t];
    float* z = out + (size_t)B * NF * G * SL + (size_t)B * SL;
    for (int i = t; i < DH; i += 512) {
        z[(size_t)b * DH + i] = 0.f;
        z[(size_t)B * DH + (size_t)b * DH + i] = 0.f;
    }

    // reset ordering state for the next replay (each block resets its own b)
    if (t == 0) {
        g_ctr_q[b] = 0u;
        g_bitP_done[b] = 0u;
    }
}

// ============================================================================
extern "C" void kernel_launch(void* const* d_in, const int* in_sizes, int n_in,
                              void* d_out, int out_size)
{
    const float* feat_edge = (const float*)d_in[2];
    const float* c_i       = (const float*)d_in[3];
    const float* relmask   = (const float*)d_in[4];
    const float* att_stack = (const float*)d_in[5];
    const float* stack_ptr = (const float*)d_in[6];
    const float* map_c_w   = (const float*)d_in[8];
    const float* map_c_b   = (const float*)d_in[9];
    float* out = (float*)d_out;

    k2_fused<<<544 + B * NF, 256>>>(relmask, feat_edge, c_i, map_c_w, map_c_b,
                                    att_stack, stack_ptr);
    k3_final<<<B, 512>>>(att_stack, stack_ptr, out);
}

// round 12
// speedup vs baseline: 1.0786x; 1.0786x over previous
#include <cuda_runtime.h>
#include <math.h>

#define B   32
#define NF  128
#define DE  256
#define DH  512
#define G   2
#define SL  8

// ---- device scratch (no allocations allowed) ----
__device__ float g_query[B * DE];
__device__ float g_attin[B * NF * G];
__device__ float g_P[B * NF * NF];       // M @ M (integer counts as float)
__device__ float g_R[B * NF * NF];       // 0.81*M + 0.729*P
__device__ float g_finalT[B * NF * NF];  // final mask, transposed [b][m][n]
__device__ float g_sig[B * NF * NF];     // sigmoid(fe . q), layout [b][m][n]
__device__ float g_attout[B * NF * G];
// k3 cross-block state (re-initialized by k1 every replay, before k3 runs)
__device__ unsigned g_normbits[B][G];
__device__ unsigned g_cnt3[B];

__device__ __forceinline__ void cp_async16(void* smem_dst, const void* gmem_src) {
    unsigned sa = (unsigned)__cvta_generic_to_shared(smem_dst);
    asm volatile("cp.async.ca.shared.global [%0], [%1], 16;" :: "r"(sa), "l"(gmem_src));
}

// ============================================================================
// Kernel 1: grid(288), block(256).
//   bid < 256 : query tile — c_i fetched via cp.async overlapped with the
//               16 independent float4 W loads (critical path = max, not sum).
//   bid >= 256: bitP — MLP-8 ballot pack, bit-transpose, popcount P = M@M,
//               R = 0.81M + 0.729P, att_in.  Also re-inits k3 state.
// ============================================================================
__global__ __launch_bounds__(256) void k1_query_bitP(
    const float* __restrict__ relmask,
    const float* __restrict__ c_i, const float* __restrict__ W,
    const float* __restrict__ bias,
    const float* __restrict__ att_stack, const float* __restrict__ stack_ptr)
{
    int bid = blockIdx.x;
    int t = threadIdx.x;

    if (bid < 256) {
        // ---------------- query tile ----------------
        int b  = bid >> 3;
        int d0 = (bid & 7) * 32;
        __shared__ __align__(16) float qc[DH];

        // c_i -> smem via cp.async (128 float4; threads 0-127)
        if (t < 128)
            cp_async16((float4*)qc + t, (const float4*)(c_i + b * DH) + t);
        asm volatile("cp.async.commit_group;");

        int w = t >> 5, lane = t & 31;

        // W preload overlaps the c_i fetch (independent)
        float4 wv[4][4];
        #pragma unroll
        for (int i = 0; i < 4; i++) {
            int d = d0 + w * 4 + i;
            const float4* Wr = (const float4*)(W + (size_t)d * DH);
            #pragma unroll
            for (int jj = 0; jj < 4; jj++)
                wv[i][jj] = Wr[lane + 32 * jj];
        }
        asm volatile("cp.async.wait_group 0;");
        __syncthreads();

        const float4* qc4 = (const float4*)qc;
        #pragma unroll
        for (int i = 0; i < 4; i++) {
            int d = d0 + w * 4 + i;
            float s = 0.f;
            #pragma unroll
            for (int jj = 0; jj < 4; jj++) {
                float4 q = qc4[lane + 32 * jj];
                s += wv[i][jj].x * q.x + wv[i][jj].y * q.y
                   + wv[i][jj].z * q.z + wv[i][jj].w * q.w;
            }
            #pragma unroll
            for (int o = 16; o; o >>= 1) s += __shfl_xor_sync(~0u, s, o);
            if (lane == 0) g_query[b * DE + d] = s + bias[d];
        }
        return;
    }

    // ---------------- bitP (+ att_in, + k3 state init) ----------------
    int b = bid - 256;
    const float* Mb = relmask + (size_t)b * NF * NF;

    __shared__ unsigned rowbits[NF][4];
    __shared__ unsigned colbits[NF][5];

    int w = t >> 5, lane = t & 31;

    if (t == 0) {
        g_normbits[b][0] = 0x3F800000u;   // 1.0f
        g_normbits[b][1] = 0x3F800000u;
        g_cnt3[b] = 0u;
    }

    // pack rows: batch 8 loads before ballots -> MLP 8
    #pragma unroll
    for (int g8 = 0; g8 < 8; g8++) {
        float v[8];
        #pragma unroll
        for (int i = 0; i < 8; i++) {
            int Wd = w + 8 * (8 * g8 + i);
            int r = Wd >> 2, ww = Wd & 3;
            v[i] = Mb[r * NF + ww * 32 + lane];
        }
        #pragma unroll
        for (int i = 0; i < 8; i++) {
            int Wd = w + 8 * (8 * g8 + i);
            int r = Wd >> 2, ww = Wd & 3;
            unsigned bal = __ballot_sync(~0u, v[i] != 0.f);
            if (lane == 0) rowbits[r][ww] = bal;
        }
    }

    // att_in
    {
        int n = t >> 1, g = t & 1;
        const float* as = att_stack + (((size_t)b * NF + n) * G + g) * SL;
        const float* sp = stack_ptr + b * SL;
        float s = 0.f;
        #pragma unroll
        for (int ss = 0; ss < SL; ss++) s += as[ss] * sp[ss];
        g_attin[(b * NF + n) * G + g] = s;
    }
    __syncthreads();

    // bit transpose
    for (int p = t; p < 512; p += 256) {
        int m = p >> 2, ww = p & 3;
        unsigned x = 0;
        #pragma unroll
        for (int j = 0; j < 32; j++)
            x |= (((rowbits[32 * ww + j][m >> 5] >> (m & 31)) & 1u) << j);
        colbits[m][ww] = x;
    }
    __syncthreads();

    float* Pb = g_P + (size_t)b * NF * NF;
    float* Rb = g_R + (size_t)b * NF * NF;
    for (int o = t; o < NF * NF; o += 256) {
        int n = o >> 7, m = o & 127;
        unsigned c = __popc(rowbits[n][0] & colbits[m][0])
                   + __popc(rowbits[n][1] & colbits[m][1])
                   + __popc(rowbits[n][2] & colbits[m][2])
                   + __popc(rowbits[n][3] & colbits[m][3]);
        float p = (float)c;
        float mm = (float)((rowbits[n][m >> 5] >> (m & 31)) & 1u);
        Pb[o] = p;
        Rb[o] = 0.81f * mm + 0.729f * p;
    }
}

// ============================================================================
// Kernel 2: combined launch (unchanged from round 10 best).
//   bid < 256  : prepB — final = M + 0.9P + P@R, write final^T.
//   bid >= 256 : sigma stream.
// ============================================================================
__global__ __launch_bounds__(256) void k2_prepB_sigma(
    const float* __restrict__ relmask, const float* __restrict__ fe)
{
    __shared__ __align__(16) char shraw[49152];
    int bid = blockIdx.x;
    int t = threadIdx.x;

    if (bid < 256) {
        int b  = bid >> 3;
        int n0 = (bid & 7) * 16;
        const float* Pb = g_P + (size_t)b * NF * NF;
        const float* Rb = g_R + (size_t)b * NF * NF;
        const float* Mb = relmask + (size_t)b * NF * NF;

        float (*csh)[NF] = (float(*)[NF])shraw;
        float (*msm)[NF] = (float(*)[NF])(shraw + 8192);
        float (*msh)[32][NF] = (float(*)[32][NF])(shraw + 16384);

        {
            const float4* srcP = (const float4*)(Pb + (size_t)n0 * NF);
            const float4* srcM = (const float4*)(Mb + (size_t)n0 * NF);
            float4* dstP = (float4*)&csh[0][0];
            float4* dstM = (float4*)&msm[0][0];
            cp_async16(dstP + t,       srcP + t);
            cp_async16(dstP + t + 256, srcP + t + 256);
            cp_async16(dstM + t,       srcM + t);
            cp_async16(dstM + t + 256, srcM + t + 256);
        }
        {
            const float4* src = (const float4*)Rb;
            float4* dst = (float4*)&msh[0][0][0];
            #pragma unroll
            for (int i = 0; i < 4; i++)
                cp_async16(dst + t + 256 * i, src + t + 256 * i);
        }
        asm volatile("cp.async.commit_group;");
        asm volatile("cp.async.wait_group 0;");
        __syncthreads();

        int tn = (t >> 5) * 2;
        int tm = (t & 31) * 4;

        float acc0[4] = {}, acc1[4] = {};
        for (int kt = 0; kt < 4; kt++) {
            if (kt < 3) {
                const float4* src = (const float4*)(Rb + (size_t)(kt + 1) * 32 * NF);
                float4* dst = (float4*)&msh[(kt + 1) & 1][0][0];
                #pragma unroll
                for (int i = 0; i < 4; i++)
                    cp_async16(dst + t + 256 * i, src + t + 256 * i);
                asm volatile("cp.async.commit_group;");
                asm volatile("cp.async.wait_group 1;");
            } else {
                asm volatile("cp.async.wait_group 0;");
            }
            __syncthreads();

            const float (*mb)[NF] = msh[kt & 1];
            #pragma unroll
            for (int kk4 = 0; kk4 < 8; kk4++) {
                float cva[4], cvb[4];
                *(float4*)cva = *(const float4*)&csh[tn + 0][kt * 32 + kk4 * 4];
                *(float4*)cvb = *(const float4*)&csh[tn + 1][kt * 32 + kk4 * 4];
                #pragma unroll
                for (int j = 0; j < 4; j++) {
                    float4 mv = *(const float4*)&mb[kk4 * 4 + j][tm];
                    acc0[0] += cva[j] * mv.x; acc0[1] += cva[j] * mv.y;
                    acc0[2] += cva[j] * mv.z; acc0[3] += cva[j] * mv.w;
                    acc1[0] += cvb[j] * mv.x; acc1[1] += cvb[j] * mv.y;
                    acc1[2] += cvb[j] * mv.z; acc1[3] += cvb[j] * mv.w;
                }
            }
            __syncthreads();
        }

        float4 f0, f1;
        {
            float4 mm = *(const float4*)&msm[tn + 0][tm];
            float4 pp = *(const float4*)&csh[tn + 0][tm];
            f0.x = mm.x + 0.9f * pp.x + acc0[0];
            f0.y = mm.y + 0.9f * pp.y + acc0[1];
            f0.z = mm.z + 0.9f * pp.z + acc0[2];
            f0.w = mm.w + 0.9f * pp.w + acc0[3];
            mm = *(const float4*)&msm[tn + 1][tm];
            pp = *(const float4*)&csh[tn + 1][tm];
            f1.x = mm.x + 0.9f * pp.x + acc1[0];
            f1.y = mm.y + 0.9f * pp.y + acc1[1];
            f1.z = mm.z + 0.9f * pp.z + acc1[2];
            f1.w = mm.w + 0.9f * pp.w + acc1[3];
        }
        __syncthreads();
        *(float4*)&csh[tn + 0][tm] = f0;
        *(float4*)&csh[tn + 1][tm] = f1;
        __syncthreads();
        {
            int m = t >> 1, half = (t & 1) * 8;
            float v[8];
            #pragma unroll
            for (int i = 0; i < 8; i++) v[i] = csh[half + i][m];
            float* dstT = g_finalT + ((size_t)b * NF + m) * NF + n0 + half;
            *(float4*)&dstT[0] = make_float4(v[0], v[1], v[2], v[3]);
            *(float4*)&dstT[4] = make_float4(v[4], v[5], v[6], v[7]);
        }
        return;
    }

    // ---------------- sigma stream ----------------
    int id = bid - 256;
    int b = id >> 7;
    int m = id & 127;
    float* qsh = (float*)shraw;
    float* sig = qsh + DE;

    qsh[t] = g_query[b * DE + t];
    __syncthreads();

    int w = t >> 5, lane = t & 31;
    int qq = lane >> 3, sub = lane & 7;
    const float4* qp = (const float4*)qsh;
    const float* febase = fe + (((size_t)b * NF) * NF + m) * DE;

    float4 cur[8];
    {
        const float4* row = (const float4*)(febase + (size_t)(w + 8 * qq) * NF * DE);
        #pragma unroll
        for (int c = 0; c < 8; c++) cur[c] = __ldcs(&row[sub + 8 * c]);
    }

    #pragma unroll
    for (int j = 0; j < 4; j++) {
        float4 nxt[8];
        if (j < 3) {
            int n2 = w + 8 * (4 * (j + 1) + qq);
            const float4* row = (const float4*)(febase + (size_t)n2 * NF * DE);
            #pragma unroll
            for (int c = 0; c < 8; c++) nxt[c] = __ldcs(&row[sub + 8 * c]);
        }

        float sA = 0.f, sB = 0.f;
        #pragma unroll
        for (int c = 0; c < 8; c += 2) {
            float4 q0 = qp[sub + 8 * c];
            float4 q1 = qp[sub + 8 * (c + 1)];
            sA += cur[c].x * q0.x + cur[c].y * q0.y
                + cur[c].z * q0.z + cur[c].w * q0.w;
            sB += cur[c+1].x * q1.x + cur[c+1].y * q1.y
                + cur[c+1].z * q1.z + cur[c+1].w * q1.w;
        }
        float s = sA + sB;
        s += __shfl_xor_sync(~0u, s, 1);
        s += __shfl_xor_sync(~0u, s, 2);
        s += __shfl_xor_sync(~0u, s, 4);
        int n = w + 8 * (4 * j + qq);
        if (sub == 0) sig[n] = 1.f / (1.f + __expf(-s));

        #pragma unroll
        for (int c = 0; c < 8; c++) cur[c] = nxt[c];
    }
    __syncthreads();
    if (t < NF)
        g_sig[((size_t)b * NF + m) * NF + t] = sig[t];
}

// ============================================================================
// Kernel 3: grid(256), block(256).  Block (b, chunk) contracts 16 m-rows,
// atomicMax's the per-(b,g) norm, then the LAST block per b blends + writes
// all outputs for that b (counter handoff; no extra launch, no spinning).
// ============================================================================
__global__ __launch_bounds__(256) void k3_final(
    const float* __restrict__ att_stack, const float* __restrict__ stack_ptr,
    float* __restrict__ out)
{
    int bid = blockIdx.x;
    int b  = bid >> 3;
    int m0 = (bid & 7) * 16;
    int t = threadIdx.x, w = t >> 5, lane = t & 31;

    __shared__ float ash[NF * G];
    __shared__ unsigned sflag;
    ash[t] = g_attin[b * NF * G + t];
    __syncthreads();

    const float4* ap = (const float4*)ash;
    float4 a01 = ap[2 * lane], a23 = ap[2 * lane + 1];

    float lmax0 = 0.f, lmax1 = 0.f;
    #pragma unroll
    for (int r = 0; r < 2; r++) {
        int m = m0 + w * 2 + r;
        const float4* fr = (const float4*)(g_finalT + ((size_t)b * NF + m) * NF);
        const float4* sr = (const float4*)(g_sig    + ((size_t)b * NF + m) * NF);
        float4 f = fr[lane];
        float4 s = sr[lane];
        float w0 = f.x * s.x, w1 = f.y * s.y, w2 = f.z * s.z, w3 = f.w * s.w;
        float p0 = w0 * a01.x + w1 * a01.z + w2 * a23.x + w3 * a23.z;
        float p1 = w0 * a01.y + w1 * a01.w + w2 * a23.y + w3 * a23.w;
        #pragma unroll
        for (int o = 16; o; o >>= 1) {
            p0 += __shfl_xor_sync(~0u, p0, o);
            p1 += __shfl_xor_sync(~0u, p1, o);
        }
        if (lane == 0) {
            g_attout[((size_t)b * NF + m) * G + 0] = p0;
            g_attout[((size_t)b * NF + m) * G + 1] = p1;
            lmax0 = fmaxf(lmax0, p0);
            lmax1 = fmaxf(lmax1, p1);
        }
    }
    if (lane == 0) {
        // values are clamped >= 0, so uint-bit atomicMax == float max
        atomicMax(&g_normbits[b][0], __float_as_uint(lmax0));
        atomicMax(&g_normbits[b][1], __float_as_uint(lmax1));
    }
    __threadfence();
    __syncthreads();
    if (t == 0) sflag = atomicAdd(&g_cnt3[b], 1u);
    __syncthreads();
    if (sflag != 7u) return;

    // -------- last block for this b: blend + all outputs --------
    __threadfence();
    __shared__ float attb[NF * G];
    __shared__ float sps[SL];
    attb[t] = *((volatile float*)&g_attout[b * NF * G + t]);
    if (t < SL) sps[t] = stack_ptr[b * SL + t];
    float n0f = __uint_as_float(*((volatile unsigned*)&g_normbits[b][0]));
    float n1f = __uint_as_float(*((volatile unsigned*)&g_normbits[b][1]));
    __syncthreads();

    const float* asb = att_stack + (size_t)b * NF * G * SL;
    float* ob = out + (size_t)b * NF * G * SL;
    for (int idx = t; idx < NF * G * SL; idx += 256) {
        int s = idx & 7;
        int g = (idx >> 3) & 1;
        int n = idx >> 4;
        float a  = attb[n * G + g] / (g ? n1f : n0f);
        float sp = sps[s];
        ob[idx] = a * sp + asb[idx] * (1.f - sp);
    }
    if (t < SL) out[(size_t)B * NF * G * SL + b * SL + t] = sps[t];
    float* z = out + (size_t)B * NF * G * SL + (size_t)B * SL;
    for (int i = t; i < DH; i += 256) {
        z[(size_t)b * DH + i] = 0.f;
        z[(size_t)B * DH + (size_t)b * DH + i] = 0.f;
    }
}

// ============================================================================
extern "C" void kernel_launch(void* const* d_in, const int* in_sizes, int n_in,
                              void* d_out, int out_size)
{
    const float* feat_edge = (const float*)d_in[2];
    const float* c_i       = (const float*)d_in[3];
    const float* relmask   = (const float*)d_in[4];
    const float* att_stack = (const float*)d_in[5];
    const float* stack_ptr = (const float*)d_in[6];
    const float* map_c_w   = (const float*)d_in[8];
    const float* map_c_b   = (const float*)d_in[9];
    float* out = (float*)d_out;

    k1_query_bitP<<<288, 256>>>(relmask, c_i, map_c_w, map_c_b,
                                att_stack, stack_ptr);
    k2_prepB_sigma<<<256 + B * NF, 256>>>(relmask, feat_edge);
    k3_final<<<256, 256>>>(att_stack, stack_ptr, out);
}

// round 13
// speedup vs baseline: 1.1244x; 1.0424x over previous
#include <cuda_runtime.h>
#include <math.h>

#define B   32
#define NF  128
#define DE  256
#define DH  512
#define G   2
#define SL  8

// ---- device scratch (no allocations allowed) ----
__device__ float g_query[B * DE];
__device__ float g_finalT[B * NF * NF];  // final mask, transposed [b][m][n]
__device__ float g_sig[B * NF * NF];     // sigmoid(fe . q), layout [b][m][n]

__device__ __forceinline__ void cp_async16(void* smem_dst, const void* gmem_src) {
    unsigned sa = (unsigned)__cvta_generic_to_shared(smem_dst);
    asm volatile("cp.async.ca.shared.global [%0], [%1], 16;" :: "r"(sa), "l"(gmem_src));
}

// ============================================================================
// Kernel 1: query only.  grid(256), block(256).
// Block (b = bid>>3, dchunk = bid&7) computes query[b, dchunk*32 .. +32).
// c_i via cp.async overlapped with 16 independent float4 W loads per thread.
// ============================================================================
__global__ __launch_bounds__(256) void k1_query(
    const float* __restrict__ c_i, const float* __restrict__ W,
    const float* __restrict__ bias)
{
    int bid = blockIdx.x;
    int t = threadIdx.x;
    int b  = bid >> 3;
    int d0 = (bid & 7) * 32;
    __shared__ __align__(16) float qc[DH];

    if (t < 128)
        cp_async16((float4*)qc + t, (const float4*)(c_i + b * DH) + t);
    asm volatile("cp.async.commit_group;");

    int w = t >> 5, lane = t & 31;

    float4 wv[4][4];
    #pragma unroll
    for (int i = 0; i < 4; i++) {
        int d = d0 + w * 4 + i;
        const float4* Wr = (const float4*)(W + (size_t)d * DH);
        #pragma unroll
        for (int jj = 0; jj < 4; jj++)
            wv[i][jj] = Wr[lane + 32 * jj];
    }
    asm volatile("cp.async.wait_group 0;");
    __syncthreads();

    const float4* qc4 = (const float4*)qc;
    #pragma unroll
    for (int i = 0; i < 4; i++) {
        int d = d0 + w * 4 + i;
        float s = 0.f;
        #pragma unroll
        for (int jj = 0; jj < 4; jj++) {
            float4 q = qc4[lane + 32 * jj];
            s += wv[i][jj].x * q.x + wv[i][jj].y * q.y
               + wv[i][jj].z * q.z + wv[i][jj].w * q.w;
        }
        #pragma unroll
        for (int o = 16; o; o >>= 1) s += __shfl_xor_sync(~0u, s, o);
        if (lane == 0) g_query[b * DE + d] = s + bias[d];
    }
}

// ============================================================================
// Kernel 2: combined launch, grid(256 + B*NF), block(256).
//   bid < 256  : prepB (SELF-CONTAINED) — bit-pack M, synthesize P/R operands
//                from bits in smem, final = M + 0.9P + P@R, write final^T.
//                Only global input: relmask.  No dependency on k1.
//   bid >= 256 : sigma stream — sig[b,m,n] = sigmoid(fe[b,n,m,:].q[b,:]).
// ============================================================================
__global__ __launch_bounds__(256) void k2_prepB_sigma(
    const float* __restrict__ relmask, const float* __restrict__ fe)
{
    __shared__ __align__(16) char shraw[49152];
    int bid = blockIdx.x;
    int t = threadIdx.x;

    if (bid < 256) {
        // ---------------- self-contained prepB ----------------
        int b  = bid >> 3;
        int n0 = (bid & 7) * 16;
        const float* Mb = relmask + (size_t)b * NF * NF;

        unsigned (*rowbits)[4] = (unsigned(*)[4])shraw;            // 2.0KB
        unsigned (*colbits)[5] = (unsigned(*)[5])(shraw + 2048);   // 2.5KB
        float (*csh)[NF] = (float(*)[NF])(shraw + 4608);           // 8KB: P rows
        float (*msm)[NF] = (float(*)[NF])(shraw + 12800);          // 8KB: M rows
        float (*msh)[NF] = (float(*)[NF])(shraw + 20992);          // 16KB: R tile

        int w = t >> 5, lane = t & 31;

        // bit-pack M: batch 8 loads before ballots -> MLP 8
        #pragma unroll
        for (int g8 = 0; g8 < 8; g8++) {
            float v[8];
            #pragma unroll
            for (int i = 0; i < 8; i++) {
                int Wd = w + 8 * (8 * g8 + i);
                int r = Wd >> 2, ww = Wd & 3;
                v[i] = Mb[r * NF + ww * 32 + lane];
            }
            #pragma unroll
            for (int i = 0; i < 8; i++) {
                int Wd = w + 8 * (8 * g8 + i);
                int r = Wd >> 2, ww = Wd & 3;
                unsigned bal = __ballot_sync(~0u, v[i] != 0.f);
                if (lane == 0) rowbits[r][ww] = bal;
            }
        }
        __syncthreads();

        // bit transpose
        for (int p = t; p < 512; p += 256) {
            int m = p >> 2, ww = p & 3;
            unsigned x = 0;
            #pragma unroll
            for (int j = 0; j < 32; j++)
                x |= (((rowbits[32 * ww + j][m >> 5] >> (m & 31)) & 1u) << j);
            colbits[m][ww] = x;
        }
        __syncthreads();

        // left operand P rows + M rows for this block's 16 output rows
        for (int o = t; o < 16 * NF; o += 256) {
            int i = o >> 7, m = o & 127;
            int n = n0 + i;
            unsigned c = __popc(rowbits[n][0] & colbits[m][0])
                       + __popc(rowbits[n][1] & colbits[m][1])
                       + __popc(rowbits[n][2] & colbits[m][2])
                       + __popc(rowbits[n][3] & colbits[m][3]);
            csh[i][m] = (float)c;
            msm[i][m] = (float)((rowbits[n][m >> 5] >> (m & 31)) & 1u);
        }
        __syncthreads();

        int tn = (t >> 5) * 2;
        int tm = (t & 31) * 4;

        float acc0[4] = {}, acc1[4] = {};
        for (int kt = 0; kt < 4; kt++) {
            // synthesize R k-tile from bits: R[k][m] = 0.81*M + 0.729*P
            for (int o = t; o < 32 * NF; o += 256) {
                int kk = o >> 7, m = o & 127;
                int k = kt * 32 + kk;
                unsigned c = __popc(rowbits[k][0] & colbits[m][0])
                           + __popc(rowbits[k][1] & colbits[m][1])
                           + __popc(rowbits[k][2] & colbits[m][2])
                           + __popc(rowbits[k][3] & colbits[m][3]);
                float mmv = (float)((rowbits[k][m >> 5] >> (m & 31)) & 1u);
                msh[kk][m] = 0.81f * mmv + 0.729f * (float)c;
            }
            __syncthreads();

            #pragma unroll
            for (int kk4 = 0; kk4 < 8; kk4++) {
                float cva[4], cvb[4];
                *(float4*)cva = *(const float4*)&csh[tn + 0][kt * 32 + kk4 * 4];
                *(float4*)cvb = *(const float4*)&csh[tn + 1][kt * 32 + kk4 * 4];
                #pragma unroll
                for (int j = 0; j < 4; j++) {
                    float4 mv = *(const float4*)&msh[kk4 * 4 + j][tm];
                    acc0[0] += cva[j] * mv.x; acc0[1] += cva[j] * mv.y;
                    acc0[2] += cva[j] * mv.z; acc0[3] += cva[j] * mv.w;
                    acc1[0] += cvb[j] * mv.x; acc1[1] += cvb[j] * mv.y;
                    acc1[2] += cvb[j] * mv.z; acc1[3] += cvb[j] * mv.w;
                }
            }
            __syncthreads();
        }

        // f = M + 0.9*P + acc
        float4 f0, f1;
        {
            float4 mm = *(const float4*)&msm[tn + 0][tm];
            float4 pp = *(const float4*)&csh[tn + 0][tm];
            f0.x = mm.x + 0.9f * pp.x + acc0[0];
            f0.y = mm.y + 0.9f * pp.y + acc0[1];
            f0.z = mm.z + 0.9f * pp.z + acc0[2];
            f0.w = mm.w + 0.9f * pp.w + acc0[3];
            mm = *(const float4*)&msm[tn + 1][tm];
            pp = *(const float4*)&csh[tn + 1][tm];
            f1.x = mm.x + 0.9f * pp.x + acc1[0];
            f1.y = mm.y + 0.9f * pp.y + acc1[1];
            f1.z = mm.z + 0.9f * pp.z + acc1[2];
            f1.w = mm.w + 0.9f * pp.w + acc1[3];
        }
        __syncthreads();
        *(float4*)&csh[tn + 0][tm] = f0;
        *(float4*)&csh[tn + 1][tm] = f1;
        __syncthreads();
        {
            int m = t >> 1, half = (t & 1) * 8;
            float v[8];
            #pragma unroll
            for (int i = 0; i < 8; i++) v[i] = csh[half + i][m];
            float* dstT = g_finalT + ((size_t)b * NF + m) * NF + n0 + half;
            *(float4*)&dstT[0] = make_float4(v[0], v[1], v[2], v[3]);
            *(float4*)&dstT[4] = make_float4(v[4], v[5], v[6], v[7]);
        }
        return;
    }

    // ---------------- sigma stream ----------------
    int id = bid - 256;
    int b = id >> 7;
    int m = id & 127;
    float* qsh = (float*)shraw;
    float* sig = qsh + DE;

    qsh[t] = g_query[b * DE + t];
    __syncthreads();

    int w = t >> 5, lane = t & 31;
    int qq = lane >> 3, sub = lane & 7;
    const float4* qp = (const float4*)qsh;
    const float* febase = fe + (((size_t)b * NF) * NF + m) * DE;

    float4 cur[8];
    {
        const float4* row = (const float4*)(febase + (size_t)(w + 8 * qq) * NF * DE);
        #pragma unroll
        for (int c = 0; c < 8; c++) cur[c] = __ldcs(&row[sub + 8 * c]);
    }

    #pragma unroll
    for (int j = 0; j < 4; j++) {
        float4 nxt[8];
        if (j < 3) {
            int n2 = w + 8 * (4 * (j + 1) + qq);
            const float4* row = (const float4*)(febase + (size_t)n2 * NF * DE);
            #pragma unroll
            for (int c = 0; c < 8; c++) nxt[c] = __ldcs(&row[sub + 8 * c]);
        }

        float sA = 0.f, sB = 0.f;
        #pragma unroll
        for (int c = 0; c < 8; c += 2) {
            float4 q0 = qp[sub + 8 * c];
            float4 q1 = qp[sub + 8 * (c + 1)];
            sA += cur[c].x * q0.x + cur[c].y * q0.y
                + cur[c].z * q0.z + cur[c].w * q0.w;
            sB += cur[c+1].x * q1.x + cur[c+1].y * q1.y
                + cur[c+1].z * q1.z + cur[c+1].w * q1.w;
        }
        float s = sA + sB;
        s += __shfl_xor_sync(~0u, s, 1);
        s += __shfl_xor_sync(~0u, s, 2);
        s += __shfl_xor_sync(~0u, s, 4);
        int n = w + 8 * (4 * j + qq);
        if (sub == 0) sig[n] = 1.f / (1.f + __expf(-s));

        #pragma unroll
        for (int c = 0; c < 8; c++) cur[c] = nxt[c];
    }
    __syncthreads();
    if (t < NF)
        g_sig[((size_t)b * NF + m) * NF + t] = sig[t];
}

// ============================================================================
// Kernel 3: att_in (inline) + masked contraction + norm + blend + outputs.
// grid(B), block(512).  Each warp handles 8 m-rows.
// ============================================================================
__global__ __launch_bounds__(512) void k3_final(
    const float* __restrict__ att_stack, const float* __restrict__ stack_ptr,
    float* __restrict__ out)
{
    int b = blockIdx.x;
    int t = threadIdx.x;
    __shared__ __align__(16) float asts[NF * G * SL];   // 8KB att_stack[b]
    __shared__ float ash[NF * G];
    __shared__ float att[NF * G];
    __shared__ float norm[G];
    __shared__ float sps[SL];

    ((float4*)asts)[t] = ((const float4*)(att_stack + (size_t)b * NF * G * SL))[t];
    if (t < SL) sps[t] = stack_ptr[b * SL + t];
    __syncthreads();

    // att_in inline: ash[n*G+g] = sum_s asts[(n*G+g)*SL+s] * sps[s]
    if (t < NF * G) {
        float s = 0.f;
        #pragma unroll
        for (int ss = 0; ss < SL; ss++) s += asts[t * SL + ss] * sps[ss];
        ash[t] = s;
    }
    __syncthreads();

    int w = t >> 5, lane = t & 31;
    const float4* ap = (const float4*)ash;
    float4 a01 = ap[2 * lane], a23 = ap[2 * lane + 1];

    #pragma unroll
    for (int r = 0; r < 8; r++) {
        int m = w + 16 * r;
        const float4* fr = (const float4*)(g_finalT + ((size_t)b * NF + m) * NF);
        const float4* sr = (const float4*)(g_sig    + ((size_t)b * NF + m) * NF);
        float4 f = fr[lane];
        float4 s = sr[lane];
        float w0 = f.x * s.x, w1 = f.y * s.y, w2 = f.z * s.z, w3 = f.w * s.w;
        float p0 = w0 * a01.x + w1 * a01.z + w2 * a23.x + w3 * a23.z;
        float p1 = w0 * a01.y + w1 * a01.w + w2 * a23.y + w3 * a23.w;
        #pragma unroll
        for (int o = 16; o; o >>= 1) {
            p0 += __shfl_xor_sync(~0u, p0, o);
            p1 += __shfl_xor_sync(~0u, p1, o);
        }
        if (lane == 0) { att[m * 2] = p0; att[m * 2 + 1] = p1; }
    }
    __syncthreads();

    if (t < 64) {
        int g = t >> 5, ln = t & 31;
        float mx = -1e30f;
        for (int i = ln; i < NF; i += 32) mx = fmaxf(mx, att[i * G + g]);
        #pragma unroll
        for (int o = 16; o; o >>= 1) mx = fmaxf(mx, __shfl_xor_sync(~0u, mx, o));
        if (ln == 0) norm[g] = (mx <= 1.f) ? 1.f : mx;
    }
    __syncthreads();

    float* ob = out + (size_t)b * NF * G * SL;
    for (int idx = t; idx < NF * G * SL; idx += 512) {
        int s = idx & 7;
        int g = (idx >> 3) & 1;
        int n = idx >> 4;
        float a  = att[n * G + g] / norm[g];
        float sp = sps[s];
        ob[idx] = a * sp + asts[idx] * (1.f - sp);
    }
    if (t < SL) out[(size_t)B * NF * G * SL + b * SL + t] = sps[t];
    float* z = out + (size_t)B * NF * G * SL + (size_t)B * SL;
    for (int i = t; i < DH; i += 512) {
        z[(size_t)b * DH + i] = 0.f;
        z[(size_t)B * DH + (size_t)b * DH + i] = 0.f;
    }
}

// ============================================================================
extern "C" void kernel_launch(void* const* d_in, const int* in_sizes, int n_in,
                              void* d_out, int out_size)
{
    const float* feat_edge = (const float*)d_in[2];
    const float* c_i       = (const float*)d_in[3];
    const float* relmask   = (const float*)d_in[4];
    const float* att_stack = (const float*)d_in[5];
    const float* stack_ptr = (const float*)d_in[6];
    const float* map_c_w   = (const float*)d_in[8];
    const float* map_c_b   = (const float*)d_in[9];
    float* out = (float*)d_out;

    k1_query<<<256, 256>>>(c_i, map_c_w, map_c_b);
    k2_prepB_sigma<<<256 + B * NF, 256>>>(relmask, feat_edge);
    k3_final<<<B, 512>>>(att_stack, stack_ptr, out);
}